// round 1
// baseline (speedup 1.0000x reference)
#include <cuda_runtime.h>

// NeuralSpectralBlock1d fused kernel (fp32, fma.f32x2 GEMM core).
// B=32, C=256, H=4096, PATCH=4, HEAD=8, DH=32, NT=4, NB=12.
// One CTA = 16 patches = 64 consecutive h-columns of one batch.

typedef unsigned long long ull;

#define THREADS 256
#define XPT_STRIDE 258   // xp_t[64][258]  (xp transposed: [col][c])
#define LTS_STRIDE 66    // lt_s[256][66]
#define ES_STRIDE  66    // enc_s/outb[64][66]
#define ASM_STRIDE 34    // Asm[64][34]

__device__ __forceinline__ void fma2(ull& d, ull a, ull b) {
    asm("fma.rn.f32x2 %0, %1, %2, %0;" : "+l"(d) : "l"(a), "l"(b));
}
__device__ __forceinline__ float hsum2(ull v) {
    float lo, hi;
    asm("mov.b64 {%0, %1}, %2;" : "=f"(lo), "=f"(hi) : "l"(v));
    return lo + hi;
}

// Tile GEMM: dst[64][64cols] = Wg[64][256] * xp_t^T + bias, K packed in f32x2 pairs.
// Thread (tr,tc): rows tr*4+i, cols tc+16j (strided cols -> conflict-free LDS).
__device__ __forceinline__ void gemm64(const float* __restrict__ Wg,
                                       const float* __restrict__ bias,
                                       const float* __restrict__ xp_t,
                                       float* __restrict__ Asm,
                                       float* __restrict__ dst,
                                       int tid, int tr, int tc)
{
    ull acc[4][4];
#pragma unroll
    for (int i = 0; i < 4; i++)
#pragma unroll
        for (int j = 0; j < 4; j++) acc[i][j] = 0ull;

    // register prefetch of first A chunk (64 x 32)
    float pre[8];
#pragma unroll
    for (int it = 0; it < 8; it++) {
        int idx = tid + it * THREADS;
        pre[it] = Wg[(idx >> 5) * 256 + (idx & 31)];
    }

#pragma unroll 1
    for (int k0 = 0; k0 < 256; k0 += 32) {
        __syncthreads();
#pragma unroll
        for (int it = 0; it < 8; it++) {
            int idx = tid + it * THREADS;
            Asm[(idx >> 5) * ASM_STRIDE + (idx & 31)] = pre[it];
        }
        if (k0 < 224) {
#pragma unroll
            for (int it = 0; it < 8; it++) {
                int idx = tid + it * THREADS;
                pre[it] = Wg[(idx >> 5) * 256 + (k0 + 32) + (idx & 31)];
            }
        }
        __syncthreads();
#pragma unroll
        for (int kk = 0; kk < 16; kk++) {
            ull a0 = *(const ull*)(Asm + (tr * 4 + 0) * ASM_STRIDE + kk * 2);
            ull a1 = *(const ull*)(Asm + (tr * 4 + 1) * ASM_STRIDE + kk * 2);
            ull a2 = *(const ull*)(Asm + (tr * 4 + 2) * ASM_STRIDE + kk * 2);
            ull a3 = *(const ull*)(Asm + (tr * 4 + 3) * ASM_STRIDE + kk * 2);
            ull b0 = *(const ull*)(xp_t + (tc     ) * XPT_STRIDE + k0 + kk * 2);
            ull b1 = *(const ull*)(xp_t + (tc + 16) * XPT_STRIDE + k0 + kk * 2);
            ull b2 = *(const ull*)(xp_t + (tc + 32) * XPT_STRIDE + k0 + kk * 2);
            ull b3 = *(const ull*)(xp_t + (tc + 48) * XPT_STRIDE + k0 + kk * 2);
            fma2(acc[0][0], a0, b0); fma2(acc[0][1], a0, b1); fma2(acc[0][2], a0, b2); fma2(acc[0][3], a0, b3);
            fma2(acc[1][0], a1, b0); fma2(acc[1][1], a1, b1); fma2(acc[1][2], a1, b2); fma2(acc[1][3], a1, b3);
            fma2(acc[2][0], a2, b0); fma2(acc[2][1], a2, b1); fma2(acc[2][2], a2, b2); fma2(acc[2][3], a2, b3);
            fma2(acc[3][0], a3, b0); fma2(acc[3][1], a3, b1); fma2(acc[3][2], a3, b2); fma2(acc[3][3], a3, b3);
        }
    }
    // all threads are past the last chunk-sync, so previous readers of dst are done
#pragma unroll
    for (int i = 0; i < 4; i++) {
        float b = bias[tr * 4 + i];
#pragma unroll
        for (int j = 0; j < 4; j++)
            dst[(tr * 4 + i) * ES_STRIDE + tc + 16 * j] = hsum2(acc[i][j]) + b;
    }
}

__global__ __launch_bounds__(THREADS, 1)
void NeuralSpectralBlock1d_4509715661385_kernel(
    const float* __restrict__ x, const float* __restrict__ weights,
    const float* __restrict__ latent, const float* __restrict__ enc_w,
    const float* __restrict__ enc_b, const float* __restrict__ dec_w,
    const float* __restrict__ dec_b, float* __restrict__ out)
{
    extern __shared__ float sm[];
    float* xp_t  = sm;                          // [64][258]
    float* lt_s  = xp_t + 64 * XPT_STRIDE;      // [256][66]
    float* enc_s = lt_s + 256 * LTS_STRIDE;     // [64][66]
    float* outb  = enc_s + 64 * ES_STRIDE;      // [64][66]
    float* Asm   = outb + 64 * ES_STRIDE;       // [64][34]
    float* w_s   = Asm + 64 * ASM_STRIDE;       // [256][24]
    float* lat_s = w_s + 256 * 24;              // [8*4*32]
    float* eb_s  = lat_s + 1024;                // [512]
    float* db_s  = eb_s + 512;                  // [256]

    const int tid = threadIdx.x;
    const int bx = blockIdx.x;
    const int batch = bx >> 6;
    const int hp0 = (bx & 63) * 16;             // first patch (within batch)
    const int h0 = hp0 * 4;                     // first h column
    const float* xg = x + (size_t)batch * 256 * 4096 + h0;
    float* og = out + (size_t)batch * 256 * 4096;

    // --- loads: x tile (transposed), weights, latent, biases ---
    for (int idx = tid; idx < 256 * 64; idx += THREADS) {
        int c = idx >> 6, j = idx & 63;
        xp_t[j * XPT_STRIDE + c] = xg[c * 4096 + j];
    }
    for (int idx = tid; idx < 256 * 24; idx += THREADS) w_s[idx] = weights[idx];
    for (int idx = tid; idx < 1024; idx += THREADS) lat_s[idx] = latent[idx];
    for (int idx = tid; idx < 512; idx += THREADS) eb_s[idx] = enc_b[idx];
    for (int idx = tid; idx < 256; idx += THREADS) db_s[idx] = dec_b[idx];
    __syncthreads();

    const int tr = tid >> 4, tc = tid & 15;
    const int ip = tid >> 4;                    // patch 0..15
    const int lane = tid & 15;
    const int la = lane >> 2, lb = lane & 3;
    const unsigned FULL = 0xFFFFFFFFu;
    const float PI_OVER_NB = 0.26179938779914943653855361527329f; // pi/12

    // ================= encoder: per-head GEMM + cross-attn + spectral =================
#pragma unroll 1
    for (int h = 0; h < 8; h++) {
        gemm64(enc_w + (size_t)(h * 64) * 256, eb_s + h * 64, xp_t, Asm, enc_s, tid, tr, tc);
        __syncthreads();

        // attn1: q = latent[h] (4x32), k[s][d]=enc_s[2d][ip*4+s], v=enc_s[2d+1][..]
        {
            const float* qv = lat_s + h * 128 + la * 32;   // q[h][tt=la][:]
            float sc = 0.f;
#pragma unroll
            for (int d = 0; d < 32; d++)
                sc += qv[d] * enc_s[(2 * d) * ES_STRIDE + ip * 4 + lb];
            float mx = sc;
            mx = fmaxf(mx, __shfl_xor_sync(FULL, mx, 1, 4));
            mx = fmaxf(mx, __shfl_xor_sync(FULL, mx, 2, 4));
            float e = __expf(sc - mx);
            float ssum = e;
            ssum += __shfl_xor_sync(FULL, ssum, 1, 4);
            ssum += __shfl_xor_sync(FULL, ssum, 2, 4);
            float av = e / ssum;
            float a4[4];
#pragma unroll
            for (int s2 = 0; s2 < 4; s2++) a4[s2] = __shfl_sync(FULL, av, la * 4 + s2, 16);

            // lane now = (tt=la, g=lb): handles d = lb + 4*dd
#pragma unroll 1
            for (int dd = 0; dd < 8; dd++) {
                int d = lb + 4 * dd;
                float ltv = lat_s[h * 128 + la * 32 + d];  // + q residual
#pragma unroll
                for (int s2 = 0; s2 < 4; s2++)
                    ltv += a4[s2] * enc_s[(2 * d + 1) * ES_STRIDE + ip * 4 + s2];
                // spectral basis via angle-addition recurrence
                int c = h * 32 + d;
                const float* wc = w_s + c * 24;
                float s1, c1;
                sincosf(ltv * PI_OVER_NB, &s1, &c1);
                float sM = 0.f, cM = 1.f;
                float add = wc[12];                        // m=0: sin=0, cos=1
#pragma unroll
                for (int m = 1; m < 12; m++) {
                    float ns = sM * c1 + cM * s1;
                    float nc = cM * c1 - sM * s1;
                    sM = ns; cM = nc;
                    add += ns * wc[m] + nc * wc[12 + m];
                }
                lt_s[c * LTS_STRIDE + ip * 4 + la] = ltv + add;
            }
        }
        __syncthreads();
    }

    // ================= decoder: per-64-row GEMM + cross-attn + residual + store =================
#pragma unroll 1
    for (int cc = 0; cc < 4; cc++) {
        gemm64(dec_w + (size_t)(cc * 64) * 256, db_s + cc * 64, xp_t, Asm, enc_s, tid, tr, tc);
        __syncthreads();

#pragma unroll 1
        for (int hh = 0; hh < 2; hh++) {
            int h = cc * 2 + hh;
            // lane = (pos=la, tt=lb)
            float sc = 0.f;
#pragma unroll
            for (int d = 0; d < 32; d++)
                sc += enc_s[(hh * 32 + d) * ES_STRIDE + ip * 4 + la] *
                      lt_s[(h * 32 + d) * LTS_STRIDE + ip * 4 + lb];
            float mx = sc;
            mx = fmaxf(mx, __shfl_xor_sync(FULL, mx, 1, 4));
            mx = fmaxf(mx, __shfl_xor_sync(FULL, mx, 2, 4));
            float e = __expf(sc - mx);
            float ssum = e;
            ssum += __shfl_xor_sync(FULL, ssum, 1, 4);
            ssum += __shfl_xor_sync(FULL, ssum, 2, 4);
            float av = e / ssum;
            float a4[4];
#pragma unroll
            for (int t2 = 0; t2 < 4; t2++) a4[t2] = __shfl_sync(FULL, av, la * 4 + t2, 16);

            // lane = (pos=la, g=lb): out[c=h*32+d][pos] = sum_t a*lt + xp
#pragma unroll 1
            for (int dd = 0; dd < 8; dd++) {
                int d = lb + 4 * dd;
                float o = 0.f;
#pragma unroll
                for (int t2 = 0; t2 < 4; t2++)
                    o += a4[t2] * lt_s[(h * 32 + d) * LTS_STRIDE + ip * 4 + t2];
                o += xp_t[(ip * 4 + la) * XPT_STRIDE + h * 32 + d];
                outb[(hh * 32 + d) * ES_STRIDE + ip * 4 + la] = o;
            }
        }
        __syncthreads();

        // scrambled un-patchify write (matches reference reshape exactly):
        // flat-per-batch index = pos*Hp*C + hp*C + c
        for (int idx = tid; idx < 64 * 64; idx += THREADS) {
            int r = idx & 63;              // local c
            int ip2 = (idx >> 6) & 15;     // patch
            int pos = idx >> 10;           // 0..3
            og[(size_t)pos * (1024 * 256) + (size_t)(hp0 + ip2) * 256 + cc * 64 + r] =
                outb[r * ES_STRIDE + ip2 * 4 + pos];
        }
        // next gemm64's internal syncs order outb/enc_s reuse
    }
}

extern "C" void kernel_launch(void* const* d_in, const int* in_sizes, int n_in,
                              void* d_out, int out_size)
{
    const float* x       = (const float*)d_in[0];
    const float* weights = (const float*)d_in[1];
    const float* latent  = (const float*)d_in[2];
    const float* enc_w   = (const float*)d_in[3];
    const float* enc_b   = (const float*)d_in[4];
    const float* dec_w   = (const float*)d_in[5];
    const float* dec_b   = (const float*)d_in[6];
    float* out = (float*)d_out;

    const size_t smem_floats =
        64 * XPT_STRIDE + 256 * LTS_STRIDE + 64 * ES_STRIDE + 64 * ES_STRIDE +
        64 * ASM_STRIDE + 256 * 24 + 1024 + 512 + 256;               // 51968
    const size_t smem_bytes = smem_floats * sizeof(float);           // 207872

    cudaFuncSetAttribute(NeuralSpectralBlock1d_4509715661385_kernel,
                         cudaFuncAttributeMaxDynamicSharedMemorySize, (int)smem_bytes);

    NeuralSpectralBlock1d_4509715661385_kernel<<<2048, THREADS, smem_bytes>>>(
        x, weights, latent, enc_w, enc_b, dec_w, dec_b, out);
}

// round 3
// speedup vs baseline: 1.4732x; 1.4732x over previous
#include <cuda_runtime.h>
#include <cuda_bf16.h>
#include <cstdint>
#include <cstring>

// NeuralSpectralBlock1d: mma.sync bf16-split (3-pass) GEMM + verified SIMT epilogue.
// B=32, C=256, H=4096, PATCH=4, HEAD=8, DH=32, NT=4, NB=12.
// CTA = 64 columns (16 patches) of one batch. Grid 2048, 256 threads, 8 warps.

#define THREADS 256

// SMEM byte offsets (dynamic smem base)
#define XTHI 0u         // x^T hi bf16 [64 n][256 k], 16B-swizzled   (32768)
#define XTLO 32768u     // x^T lo                                     (32768)
#define ABUF 65536u     // 2 x 32768 A-chunk ping/pong; epilogue stg [128][65] f32
#define LT   131072u    // lt_s f32 [256][66]                         (67584)
#define WS   198656u    // spectral weights f32 [256][24]             (24576)
#define LAT  223232u    // latent f32 [1024]
#define EB   227328u    // enc bias f32 [512]
#define DB   229376u    // dec bias f32 [256]
#define SMEM_REQ 230400u

// Pre-split weights: [kchunk 0..7][row 0..767][8 x 16B], row = enc row (0-511) / 512+dec row.
// Within a row: logical 16B cols 0-3 = hi(k0-31), 4-7 = lo(k0-31); stored col = logical ^ (row&7).
__device__ uint4 g_wsplit[8][768][8];

__global__ void prep_kernel(const float* __restrict__ enc_w, const float* __restrict__ dec_w) {
    int idx = blockIdx.x * blockDim.x + threadIdx.x;
    if (idx >= 768 * 32) return;
    int row = idx >> 5, c8 = idx & 31;           // c8: which group of 8 k
    const float* src = (row < 512) ? (enc_w + row * 256 + c8 * 8)
                                   : (dec_w + (row - 512) * 256 + c8 * 8);
    union { __nv_bfloat16 h[8]; uint4 u; } hi, lo;
#pragma unroll
    for (int i = 0; i < 8; i++) {
        float v = src[i];
        hi.h[i] = __float2bfloat16(v);
        lo.h[i] = __float2bfloat16(v - __bfloat162float(hi.h[i]));
    }
    int chunk = c8 >> 2, lc = c8 & 3;
    g_wsplit[chunk][row][lc ^ (row & 7)]       = hi.u;
    g_wsplit[chunk][row][(lc + 4) ^ (row & 7)] = lo.u;
}

static __device__ __forceinline__ uint32_t smem_u32(const void* p) {
    uint32_t a;
    asm("{ .reg .u64 t; cvta.to.shared.u64 t, %1; cvt.u32.u64 %0, t; }" : "=r"(a) : "l"(p));
    return a;
}
static __device__ __forceinline__ void ldm4(uint32_t* d, uint32_t a) {
    asm volatile("ldmatrix.sync.aligned.m8n8.x4.shared.b16 {%0,%1,%2,%3}, [%4];"
                 : "=r"(d[0]), "=r"(d[1]), "=r"(d[2]), "=r"(d[3]) : "r"(a));
}
static __device__ __forceinline__ void mma16816(float* c, const uint32_t* a, const uint32_t* b) {
    asm volatile("mma.sync.aligned.m16n8k16.row.col.f32.bf16.bf16.f32 "
                 "{%0,%1,%2,%3}, {%4,%5,%6,%7}, {%8,%9}, {%0,%1,%2,%3};"
                 : "+f"(c[0]), "+f"(c[1]), "+f"(c[2]), "+f"(c[3])
                 : "r"(a[0]), "r"(a[1]), "r"(a[2]), "r"(a[3]), "r"(b[0]), "r"(b[1]));
}

__global__ __launch_bounds__(THREADS, 1)
void NeuralSpectralBlock1d_4509715661385_kernel(
    const float* __restrict__ x, const float* __restrict__ weights,
    const float* __restrict__ latent, const float* __restrict__ enc_b,
    const float* __restrict__ dec_b, float* __restrict__ out)
{
    extern __shared__ char smem[];
    const uint32_t sb = smem_u32(smem);

    float* lt_s  = (float*)(smem + LT);    // [256][66]
    float* w_s   = (float*)(smem + WS);    // [256][24]
    float* lat_s = (float*)(smem + LAT);
    float* eb_s  = (float*)(smem + EB);
    float* db_s  = (float*)(smem + DB);
    float* stg   = (float*)(smem + ABUF);  // epilogue: [128][65]

    const int tid = threadIdx.x;
    const int wid = tid >> 5, lid = tid & 31;
    const int bx = blockIdx.x;
    const int batch = bx >> 6;
    const int hp0 = (bx & 63) * 16;
    const int h0 = hp0 * 4;
    const float* xg = x + (size_t)batch * 256 * 4096 + h0;
    float* og = out + (size_t)batch * 256 * 4096;

    // ---- load x tile -> XThi/XTlo (n-major [64][256] bf16, 16B col swizzled by n) ----
    for (int idx = tid; idx < 64 * 256; idx += THREADS) {
        int j = idx & 63, c = idx >> 6;
        float v = xg[(size_t)c * 4096 + j];
        __nv_bfloat16 hi = __float2bfloat16(v);
        __nv_bfloat16 lo = __float2bfloat16(v - __bfloat162float(hi));
        uint32_t off = (uint32_t)j * 512u + ((uint32_t)((c >> 3) ^ (j & 7)) << 4) + (uint32_t)(c & 7) * 2u;
        *(__nv_bfloat16*)(smem + XTHI + off) = hi;
        *(__nv_bfloat16*)(smem + XTLO + off) = lo;
    }
    for (int idx = tid; idx < 256 * 24; idx += THREADS) w_s[idx] = weights[idx];
    for (int idx = tid; idx < 1024; idx += THREADS) lat_s[idx] = latent[idx];
    for (int idx = tid; idx < 512; idx += THREADS) eb_s[idx] = enc_b[idx];
    for (int idx = tid; idx < 256; idx += THREADS) db_s[idx] = dec_b[idx];

    // epilogue lane roles (verified in round 1)
    const int ip = tid >> 4;
    const int lane4 = tid & 15;
    const int la = lane4 >> 2, lb = lane4 & 3;
    const unsigned FULL = 0xFFFFFFFFu;
    const float PI_OVER_NB = 0.26179938779914943653855361527329f;  // pi/12

    // ldmatrix lane-address components
    const int a_row8 = (lid & 7) + ((lid >> 3) & 1) * 8;  // A: row within 16
    const int a_half = lid >> 4;                           // A: k8 select
    const int b_n8   = (lid & 7) + ((lid >> 4) & 1) * 8;   // B: n within 16
    const int b_k8   = (lid >> 3) & 1;                     // B: k8 select

    // ================= 3 GEMM rounds: r=0,1 enc (rows r*256..), r=2 dec =================
#pragma unroll 1
    for (int r = 0; r < 3; r++) {
        float acc[2][8][4];
#pragma unroll
        for (int mt = 0; mt < 2; mt++)
#pragma unroll
            for (int nt = 0; nt < 8; nt++)
#pragma unroll
                for (int q = 0; q < 4; q++) acc[mt][nt][q] = 0.f;

        // prologue: stage chunk 0 into buffer 0
        {
            const uint4* gsrc = &g_wsplit[0][r * 256 + tid][0];
            uint32_t dstb = sb + ABUF + (uint32_t)tid * 128u;
#pragma unroll
            for (int i = 0; i < 8; i++)
                asm volatile("cp.async.cg.shared.global [%0], [%1], 16;"
                             :: "r"(dstb + i * 16), "l"(gsrc + i) : "memory");
            asm volatile("cp.async.commit_group;" ::: "memory");
        }

#pragma unroll 1
        for (int c = 0; c < 8; c++) {
            if (c < 7) {
                const uint4* gsrc = &g_wsplit[c + 1][r * 256 + tid][0];
                uint32_t dstb = sb + ABUF + (uint32_t)((c + 1) & 1) * 32768u + (uint32_t)tid * 128u;
#pragma unroll
                for (int i = 0; i < 8; i++)
                    asm volatile("cp.async.cg.shared.global [%0], [%1], 16;"
                                 :: "r"(dstb + i * 16), "l"(gsrc + i) : "memory");
                asm volatile("cp.async.commit_group;" ::: "memory");
                asm volatile("cp.async.wait_group 1;" ::: "memory");
            } else {
                asm volatile("cp.async.wait_group 0;" ::: "memory");
            }
            __syncthreads();

            const uint32_t ab = sb + ABUF + (uint32_t)(c & 1) * 32768u;
#pragma unroll
            for (int s = 0; s < 2; s++) {
                uint32_t ah[2][4], al[2][4];
#pragma unroll
                for (int mt = 0; mt < 2; mt++) {
                    int row = wid * 32 + mt * 16 + a_row8;
                    int lch = 2 * s + a_half;          // hi logical col 0..3
                    ldm4(ah[mt], ab + (uint32_t)row * 128u + ((uint32_t)(lch ^ (row & 7)) << 4));
                    int lcl = 4 + 2 * s + a_half;      // lo logical col 4..7
                    ldm4(al[mt], ab + (uint32_t)row * 128u + ((uint32_t)(lcl ^ (row & 7)) << 4));
                }
                uint32_t bh[4][4], bl[4][4];
#pragma unroll
                for (int nb = 0; nb < 4; nb++) {
                    int n = nb * 16 + b_n8;
                    int col = c * 4 + 2 * s + b_k8;    // global 16B k-col 0..31
                    uint32_t off = (uint32_t)n * 512u + ((uint32_t)(col ^ (n & 7)) << 4);
                    ldm4(bh[nb], sb + XTHI + off);
                    ldm4(bl[nb], sb + XTLO + off);
                }
#pragma unroll
                for (int mt = 0; mt < 2; mt++)
#pragma unroll
                    for (int nt = 0; nt < 8; nt++) {
                        const uint32_t* B0 = &bh[nt >> 1][(nt & 1) * 2];
                        const uint32_t* B1 = &bl[nt >> 1][(nt & 1) * 2];
                        mma16816(acc[mt][nt], ah[mt], B0);   // hi*hi
                        mma16816(acc[mt][nt], ah[mt], B1);   // hi*lo
                        mma16816(acc[mt][nt], al[mt], B0);   // lo*hi
                    }
            }
            __syncthreads();   // before next chunk overwrites the other buffer
        }

        // ---------------- dump + epilogue, two halves of 128 rows ----------------
#pragma unroll 1
        for (int e = 0; e < 2; e++) {
            if ((wid >> 2) == e) {
                int wl4 = wid & 3;
                const float* bias = (r < 2) ? (eb_s + r * 256 + e * 128) : (db_s + e * 128);
#pragma unroll
                for (int mt = 0; mt < 2; mt++) {
                    int r0 = wl4 * 32 + mt * 16 + (lid >> 2);
                    float b0 = bias[r0], b8 = bias[r0 + 8];
#pragma unroll
                    for (int nt = 0; nt < 8; nt++) {
                        int cc0 = nt * 8 + (lid & 3) * 2;
                        stg[r0 * 65 + cc0]           = acc[mt][nt][0] + b0;
                        stg[r0 * 65 + cc0 + 1]       = acc[mt][nt][1] + b0;
                        stg[(r0 + 8) * 65 + cc0]     = acc[mt][nt][2] + b8;
                        stg[(r0 + 8) * 65 + cc0 + 1] = acc[mt][nt][3] + b8;
                    }
                }
            }
            __syncthreads();

            if (r < 2) {
                // ===== encoder epilogue: 2 heads in this half =====
#pragma unroll 1
                for (int hl = 0; hl < 2; hl++) {
                    int h = r * 4 + e * 2 + hl;
                    const float* qv = lat_s + h * 128 + la * 32;
                    float sc = 0.f;
#pragma unroll
                    for (int d = 0; d < 32; d++)
                        sc += qv[d] * stg[(hl * 64 + 2 * d) * 65 + ip * 4 + lb];
                    float mx = sc;
                    mx = fmaxf(mx, __shfl_xor_sync(FULL, mx, 1, 4));
                    mx = fmaxf(mx, __shfl_xor_sync(FULL, mx, 2, 4));
                    float ex = __expf(sc - mx);
                    float ssum = ex;
                    ssum += __shfl_xor_sync(FULL, ssum, 1, 4);
                    ssum += __shfl_xor_sync(FULL, ssum, 2, 4);
                    float av = ex / ssum;
                    float a4[4];
#pragma unroll
                    for (int s2 = 0; s2 < 4; s2++) a4[s2] = __shfl_sync(FULL, av, la * 4 + s2, 16);

#pragma unroll 1
                    for (int dd = 0; dd < 8; dd++) {
                        int d = lb + 4 * dd;
                        float ltv = lat_s[h * 128 + la * 32 + d];
#pragma unroll
                        for (int s2 = 0; s2 < 4; s2++)
                            ltv += a4[s2] * stg[(hl * 64 + 2 * d + 1) * 65 + ip * 4 + s2];
                        int cch = h * 32 + d;
                        const float* wc = w_s + cch * 24;
                        float s1, c1;
                        sincosf(ltv * PI_OVER_NB, &s1, &c1);
                        float sM = 0.f, cM = 1.f;
                        float add = wc[12];
#pragma unroll
                        for (int m = 1; m < 12; m++) {
                            float ns = sM * c1 + cM * s1;
                            float nc = cM * c1 - sM * s1;
                            sM = ns; cM = nc;
                            add += ns * wc[m] + nc * wc[12 + m];
                        }
                        lt_s[cch * 66 + ip * 4 + la] = ltv + add;
                    }
                }
            } else {
                // ===== decoder epilogue: 4 heads in this half =====
#pragma unroll 1
                for (int hl = 0; hl < 4; hl++) {
                    int h = e * 4 + hl;
                    float sc = 0.f;
#pragma unroll
                    for (int d = 0; d < 32; d++)
                        sc += stg[(hl * 32 + d) * 65 + ip * 4 + la] *
                              lt_s[(h * 32 + d) * 66 + ip * 4 + lb];
                    float mx = sc;
                    mx = fmaxf(mx, __shfl_xor_sync(FULL, mx, 1, 4));
                    mx = fmaxf(mx, __shfl_xor_sync(FULL, mx, 2, 4));
                    float ex = __expf(sc - mx);
                    float ssum = ex;
                    ssum += __shfl_xor_sync(FULL, ssum, 1, 4);
                    ssum += __shfl_xor_sync(FULL, ssum, 2, 4);
                    float av = ex / ssum;
                    float a4[4];
#pragma unroll
                    for (int t2 = 0; t2 < 4; t2++) a4[t2] = __shfl_sync(FULL, av, la * 4 + t2, 16);

                    int j = ip * 4 + la;
#pragma unroll 1
                    for (int dd = 0; dd < 8; dd++) {
                        int d = lb + 4 * dd;
                        int cch = h * 32 + d;
                        float o = 0.f;
#pragma unroll
                        for (int t2 = 0; t2 < 4; t2++)
                            o += a4[t2] * lt_s[cch * 66 + ip * 4 + t2];
                        uint32_t off = (uint32_t)j * 512u +
                                       ((uint32_t)((cch >> 3) ^ (j & 7)) << 4) + (uint32_t)(cch & 7) * 2u;
                        float xr = __bfloat162float(*(__nv_bfloat16*)(smem + XTHI + off)) +
                                   __bfloat162float(*(__nv_bfloat16*)(smem + XTLO + off));
                        og[(size_t)la * 262144 + (size_t)(hp0 + ip) * 256 + cch] = o + xr;
                    }
                }
            }
            __syncthreads();   // stg reuse by next half / next round staging
        }
    }
}

extern "C" void kernel_launch(void* const* d_in, const int* in_sizes, int n_in,
                              void* d_out, int out_size)
{
    const float* x       = (const float*)d_in[0];
    const float* weights = (const float*)d_in[1];
    const float* latent  = (const float*)d_in[2];
    const float* enc_w   = (const float*)d_in[3];
    const float* enc_b   = (const float*)d_in[4];
    const float* dec_w   = (const float*)d_in[5];
    const float* dec_b   = (const float*)d_in[6];
    float* out = (float*)d_out;

    prep_kernel<<<(768 * 32 + 255) / 256, 256>>>(enc_w, dec_w);

    cudaFuncSetAttribute(NeuralSpectralBlock1d_4509715661385_kernel,
                         cudaFuncAttributeMaxDynamicSharedMemorySize, (int)SMEM_REQ);
    NeuralSpectralBlock1d_4509715661385_kernel<<<2048, THREADS, SMEM_REQ>>>(
        x, weights, latent, enc_b, dec_b, out);
}

// round 4
// speedup vs baseline: 1.9324x; 1.3117x over previous
#include <cuda_runtime.h>
#include <cuda_bf16.h>
#include <cstdint>

// NeuralSpectralBlock1d: mma.sync bf16-split (3-pass) GEMM + fused SIMT epilogue.
// Round 4: 512 threads (4 warps/SMSP) for latency hiding; parallel dump/epilogue.
// CTA = 64 columns (16 patches) of one batch. Grid 2048.

#define THREADS 512

// SMEM byte offsets
#define XTHI 0u          // x^T hi bf16 [64 n][256 k], 16B-swizzled (32768)
#define XTLO 32768u      // x^T lo                                   (32768)
#define ABUF 65536u      // GEMM: ping/pong 2x32768; epilogue: stg [256][65] f32 (66560)
#define LT   132096u     // lt_s f32 [256][66]                       (67584)
#define WS   199680u     // spectral weights f32 [256][24]           (24576)
#define LAT  224256u     // latent f32 [1024]                        (4096)
#define EB   228352u     // enc bias f32 [512]                       (2048)
#define DB   230400u     // dec bias f32 [256]                       (1024)
#define SMEM_REQ 231424u

// Pre-split weights: [kchunk 0..7][row 0..767][8 x 16B]; rows 0-511 enc, 512-767 dec.
// 16B cols: logical 0-3 = hi(k 0..31 of chunk), 4-7 = lo; stored col = logical ^ (row&7).
__device__ uint4 g_wsplit[8][768][8];

__global__ void prep_kernel(const float* __restrict__ enc_w, const float* __restrict__ dec_w) {
    int idx = blockIdx.x * blockDim.x + threadIdx.x;
    if (idx >= 768 * 32) return;
    int row = idx >> 5, c8 = idx & 31;
    const float* src = (row < 512) ? (enc_w + row * 256 + c8 * 8)
                                   : (dec_w + (row - 512) * 256 + c8 * 8);
    union { __nv_bfloat16 h[8]; uint4 u; } hi, lo;
#pragma unroll
    for (int i = 0; i < 8; i++) {
        float v = src[i];
        hi.h[i] = __float2bfloat16(v);
        lo.h[i] = __float2bfloat16(v - __bfloat162float(hi.h[i]));
    }
    int chunk = c8 >> 2, lc = c8 & 3;
    g_wsplit[chunk][row][lc ^ (row & 7)]       = hi.u;
    g_wsplit[chunk][row][(lc + 4) ^ (row & 7)] = lo.u;
}

static __device__ __forceinline__ uint32_t smem_u32(const void* p) {
    uint32_t a;
    asm("{ .reg .u64 t; cvta.to.shared.u64 t, %1; cvt.u32.u64 %0, t; }" : "=r"(a) : "l"(p));
    return a;
}
static __device__ __forceinline__ void ldm4(uint32_t* d, uint32_t a) {
    asm volatile("ldmatrix.sync.aligned.m8n8.x4.shared.b16 {%0,%1,%2,%3}, [%4];"
                 : "=r"(d[0]), "=r"(d[1]), "=r"(d[2]), "=r"(d[3]) : "r"(a));
}
static __device__ __forceinline__ void mma16816(float* c, const uint32_t* a, const uint32_t* b) {
    asm volatile("mma.sync.aligned.m16n8k16.row.col.f32.bf16.bf16.f32 "
                 "{%0,%1,%2,%3}, {%4,%5,%6,%7}, {%8,%9}, {%0,%1,%2,%3};"
                 : "+f"(c[0]), "+f"(c[1]), "+f"(c[2]), "+f"(c[3])
                 : "r"(a[0]), "r"(a[1]), "r"(a[2]), "r"(a[3]), "r"(b[0]), "r"(b[1]));
}

// stage one 32KB weight chunk (rows r*256..+255) into ABUF buffer `buf` via cp.async
static __device__ __forceinline__ void stage_chunk(uint32_t sb, int r, int chunk, int buf, int tid) {
    int row = tid >> 1, half = tid & 1;
    const uint4* gsrc = &g_wsplit[chunk][r * 256 + row][half * 4];
    uint32_t dstb = sb + ABUF + (uint32_t)buf * 32768u + (uint32_t)row * 128u + (uint32_t)half * 64u;
#pragma unroll
    for (int i = 0; i < 4; i++)
        asm volatile("cp.async.cg.shared.global [%0], [%1], 16;"
                     :: "r"(dstb + i * 16), "l"(gsrc + i) : "memory");
    asm volatile("cp.async.commit_group;" ::: "memory");
}

__global__ __launch_bounds__(THREADS, 1)
void NeuralSpectralBlock1d_4509715661385_kernel(
    const float* __restrict__ x, const float* __restrict__ weights,
    const float* __restrict__ latent, const float* __restrict__ enc_b,
    const float* __restrict__ dec_b, float* __restrict__ out)
{
    extern __shared__ char smem[];
    const uint32_t sb = smem_u32(smem);

    float* lt_s  = (float*)(smem + LT);    // [256][66]
    float* w_s   = (float*)(smem + WS);    // [256][24]
    float* lat_s = (float*)(smem + LAT);
    float* eb_s  = (float*)(smem + EB);
    float* db_s  = (float*)(smem + DB);
    float* stg   = (float*)(smem + ABUF);  // epilogue: [256][65]

    const int tid = threadIdx.x;
    const int wid = tid >> 5, lid = tid & 31;
    const int bx = blockIdx.x;
    const int batch = bx >> 6;
    const int hp0 = (bx & 63) * 16;
    const int h0 = hp0 * 4;
    const float* xg = x + (size_t)batch * 256 * 4096 + h0;
    float* og = out + (size_t)batch * 256 * 4096;

    // prefetch round-0 chunk-0 weights (overlaps with x load)
    stage_chunk(sb, 0, 0, 0, tid);

    // ---- load x tile -> XThi/XTlo (n-major [64][256] bf16, 16B col swizzled by n) ----
    for (int idx = tid; idx < 64 * 256; idx += THREADS) {
        int j = idx & 63, c = idx >> 6;
        float v = xg[(size_t)c * 4096 + j];
        __nv_bfloat16 hi = __float2bfloat16(v);
        __nv_bfloat16 lo = __float2bfloat16(v - __bfloat162float(hi));
        uint32_t off = (uint32_t)j * 512u + ((uint32_t)((c >> 3) ^ (j & 7)) << 4) + (uint32_t)(c & 7) * 2u;
        *(__nv_bfloat16*)(smem + XTHI + off) = hi;
        *(__nv_bfloat16*)(smem + XTLO + off) = lo;
    }
    for (int idx = tid; idx < 256 * 24; idx += THREADS) w_s[idx] = weights[idx];
    for (int idx = tid; idx < 1024; idx += THREADS) lat_s[idx] = latent[idx];
    for (int idx = tid; idx < 512; idx += THREADS) eb_s[idx] = enc_b[idx];
    for (int idx = tid; idx < 256; idx += THREADS) db_s[idx] = dec_b[idx];

    // epilogue lane roles
    const int g256 = tid >> 8;            // thread half-group
    const int t = tid & 255;
    const int ip = t >> 4;
    const int lane4 = t & 15;
    const int la = lane4 >> 2, lb = lane4 & 3;
    const unsigned FULL = 0xFFFFFFFFu;
    const float PI_OVER_NB = 0.26179938779914943653855361527329f;  // pi/12

    // GEMM warp roles: wm = M slice (32 rows), wn = N half (32 cols)
    const int wm = wid & 7, wn = wid >> 3;
    const int a_row8 = (lid & 7) + ((lid >> 3) & 1) * 8;
    const int a_half = lid >> 4;
    const int b_n8   = (lid & 7) + ((lid >> 4) & 1) * 8;
    const int b_k8   = (lid >> 3) & 1;

    // ================= 3 GEMM rounds: r=0,1 enc; r=2 dec =================
#pragma unroll 1
    for (int r = 0; r < 3; r++) {
        float acc[2][4][4];
#pragma unroll
        for (int mt = 0; mt < 2; mt++)
#pragma unroll
            for (int nt = 0; nt < 4; nt++)
#pragma unroll
                for (int q = 0; q < 4; q++) acc[mt][nt][q] = 0.f;

#pragma unroll 1
        for (int c = 0; c < 8; c++) {
            if (c < 7) {
                stage_chunk(sb, r, c + 1, (c + 1) & 1, tid);
                asm volatile("cp.async.wait_group 1;" ::: "memory");
            } else {
                asm volatile("cp.async.wait_group 0;" ::: "memory");
            }
            __syncthreads();

            const uint32_t ab = sb + ABUF + (uint32_t)(c & 1) * 32768u;
#pragma unroll
            for (int s = 0; s < 2; s++) {
                uint32_t ah[2][4], al[2][4];
#pragma unroll
                for (int mt = 0; mt < 2; mt++) {
                    int row = wm * 32 + mt * 16 + a_row8;
                    int lch = 2 * s + a_half;
                    ldm4(ah[mt], ab + (uint32_t)row * 128u + ((uint32_t)(lch ^ (row & 7)) << 4));
                    int lcl = 4 + 2 * s + a_half;
                    ldm4(al[mt], ab + (uint32_t)row * 128u + ((uint32_t)(lcl ^ (row & 7)) << 4));
                }
                uint32_t bh[2][4], bl[2][4];
#pragma unroll
                for (int nb = 0; nb < 2; nb++) {
                    int n = (2 * wn + nb) * 16 + b_n8;
                    int col = c * 4 + 2 * s + b_k8;
                    uint32_t off = (uint32_t)n * 512u + ((uint32_t)(col ^ (n & 7)) << 4);
                    ldm4(bh[nb], sb + XTHI + off);
                    ldm4(bl[nb], sb + XTLO + off);
                }
#pragma unroll
                for (int mt = 0; mt < 2; mt++)
#pragma unroll
                    for (int nt = 0; nt < 4; nt++) {
                        const uint32_t* B0 = &bh[nt >> 1][(nt & 1) * 2];
                        const uint32_t* B1 = &bl[nt >> 1][(nt & 1) * 2];
                        mma16816(acc[mt][nt], ah[mt], B0);   // hi*hi
                        mma16816(acc[mt][nt], ah[mt], B1);   // hi*lo
                        mma16816(acc[mt][nt], al[mt], B0);   // lo*hi
                    }
            }
            __syncthreads();
        }

        // ---------------- dump (all 16 warps) ----------------
        {
            const float* bias = (r < 2) ? (eb_s + r * 256) : db_s;
#pragma unroll
            for (int mt = 0; mt < 2; mt++) {
                int r0 = wm * 32 + mt * 16 + (lid >> 2);
                float b0 = bias[r0], b8 = bias[r0 + 8];
#pragma unroll
                for (int nt = 0; nt < 4; nt++) {
                    int cc0 = wn * 32 + nt * 8 + (lid & 3) * 2;
                    stg[r0 * 65 + cc0]           = acc[mt][nt][0] + b0;
                    stg[r0 * 65 + cc0 + 1]       = acc[mt][nt][1] + b0;
                    stg[(r0 + 8) * 65 + cc0]     = acc[mt][nt][2] + b8;
                    stg[(r0 + 8) * 65 + cc0 + 1] = acc[mt][nt][3] + b8;
                }
            }
        }
        __syncthreads();

        if (r < 2) {
            // ===== encoder epilogue: group g256 handles heads r*4+g*2 .. +1 =====
#pragma unroll 1
            for (int hl = 0; hl < 2; hl++) {
                int h = r * 4 + g256 * 2 + hl;
                int rowb = g256 * 128 + hl * 64;
                const float* qv = lat_s + h * 128 + la * 32;
                float sc = 0.f;
#pragma unroll
                for (int d = 0; d < 32; d++)
                    sc += qv[d] * stg[(rowb + 2 * d) * 65 + ip * 4 + lb];
                float mx = sc;
                mx = fmaxf(mx, __shfl_xor_sync(FULL, mx, 1, 4));
                mx = fmaxf(mx, __shfl_xor_sync(FULL, mx, 2, 4));
                float ex = __expf(sc - mx);
                float ssum = ex;
                ssum += __shfl_xor_sync(FULL, ssum, 1, 4);
                ssum += __shfl_xor_sync(FULL, ssum, 2, 4);
                float av = ex / ssum;
                float a4[4];
#pragma unroll
                for (int s2 = 0; s2 < 4; s2++) a4[s2] = __shfl_sync(FULL, av, la * 4 + s2, 16);

#pragma unroll 1
                for (int dd = 0; dd < 8; dd++) {
                    int d = lb + 4 * dd;
                    float ltv = lat_s[h * 128 + la * 32 + d];
#pragma unroll
                    for (int s2 = 0; s2 < 4; s2++)
                        ltv += a4[s2] * stg[(rowb + 2 * d + 1) * 65 + ip * 4 + s2];
                    int cch = h * 32 + d;
                    const float* wc = w_s + cch * 24;
                    float s1, c1;
                    sincosf(ltv * PI_OVER_NB, &s1, &c1);
                    float sM = 0.f, cM = 1.f;
                    float add = wc[12];
#pragma unroll
                    for (int m = 1; m < 12; m++) {
                        float ns = sM * c1 + cM * s1;
                        float nc = cM * c1 - sM * s1;
                        sM = ns; cM = nc;
                        add += ns * wc[m] + nc * wc[12 + m];
                    }
                    lt_s[cch * 66 + ip * 4 + la] = ltv + add;
                }
            }
        } else {
            // ===== decoder epilogue: group g256 handles heads g*4 .. g*4+3 =====
#pragma unroll 1
            for (int hl = 0; hl < 4; hl++) {
                int h = g256 * 4 + hl;
                int rowb = g256 * 128 + hl * 32;
                float sc = 0.f;
#pragma unroll
                for (int d = 0; d < 32; d++)
                    sc += stg[(rowb + d) * 65 + ip * 4 + la] *
                          lt_s[(h * 32 + d) * 66 + ip * 4 + lb];
                float mx = sc;
                mx = fmaxf(mx, __shfl_xor_sync(FULL, mx, 1, 4));
                mx = fmaxf(mx, __shfl_xor_sync(FULL, mx, 2, 4));
                float ex = __expf(sc - mx);
                float ssum = ex;
                ssum += __shfl_xor_sync(FULL, ssum, 1, 4);
                ssum += __shfl_xor_sync(FULL, ssum, 2, 4);
                float av = ex / ssum;
                float a4[4];
#pragma unroll
                for (int t2 = 0; t2 < 4; t2++) a4[t2] = __shfl_sync(FULL, av, la * 4 + t2, 16);

                int j = ip * 4 + la;
#pragma unroll 1
                for (int dd = 0; dd < 8; dd++) {
                    int d = lb + 4 * dd;
                    int cch = h * 32 + d;
                    float o = 0.f;
#pragma unroll
                    for (int t2 = 0; t2 < 4; t2++)
                        o += a4[t2] * lt_s[cch * 66 + ip * 4 + t2];
                    uint32_t off = (uint32_t)j * 512u +
                                   ((uint32_t)((cch >> 3) ^ (j & 7)) << 4) + (uint32_t)(cch & 7) * 2u;
                    float xr = __bfloat162float(*(__nv_bfloat16*)(smem + XTHI + off)) +
                               __bfloat162float(*(__nv_bfloat16*)(smem + XTLO + off));
                    og[(size_t)la * 262144 + (size_t)(hp0 + ip) * 256 + cch] = o + xr;
                }
            }
        }
        __syncthreads();   // stg region reused by next round's staging

        if (r < 2) stage_chunk(sb, r + 1, 0, 0, tid);   // prefetch next round chunk 0
    }
}

extern "C" void kernel_launch(void* const* d_in, const int* in_sizes, int n_in,
                              void* d_out, int out_size)
{
    const float* x       = (const float*)d_in[0];
    const float* weights = (const float*)d_in[1];
    const float* latent  = (const float*)d_in[2];
    const float* enc_w   = (const float*)d_in[3];
    const float* enc_b   = (const float*)d_in[4];
    const float* dec_w   = (const float*)d_in[5];
    const float* dec_b   = (const float*)d_in[6];
    float* out = (float*)d_out;

    prep_kernel<<<(768 * 32 + 255) / 256, 256>>>(enc_w, dec_w);

    cudaFuncSetAttribute(NeuralSpectralBlock1d_4509715661385_kernel,
                         cudaFuncAttributeMaxDynamicSharedMemorySize, (int)SMEM_REQ);
    NeuralSpectralBlock1d_4509715661385_kernel<<<2048, THREADS, SMEM_REQ>>>(
        x, weights, latent, enc_b, dec_b, out);
}

// round 5
// speedup vs baseline: 2.1508x; 1.1130x over previous
#include <cuda_runtime.h>
#include <cuda_fp16.h>
#include <cstdint>

// NeuralSpectralBlock1d: mma.sync fp16 2-pass (w hi/lo split) GEMM + fused SIMT epilogue.
// Round 5: fp16 halves tensor passes (3->2) and B-operand LDSM vs bf16-split round 4.
// CTA = 64 columns (16 patches) of one batch. Grid 2048, 512 threads.

#define THREADS 512

// SMEM byte offsets
#define XTHI 0u          // x^T fp16 [64 n][256 k], 16B-swizzled      (32768)
#define ABUF 32768u      // GEMM: ping/pong 2x32768; epilogue: stg [256][65] f32 (66560)
#define LT   99328u      // lt_s f32 [256][66]                        (67584)
#define WS   166912u     // spectral weights f32 [256][24]            (24576)
#define LAT  191488u     // latent f32 [1024]                         (4096)
#define EB   195584u     // enc bias f32 [512]                        (2048)
#define DB   197632u     // dec bias f32 [256]                        (1024)
#define SMEM_REQ 198656u

// Pre-split weights: [kchunk 0..7][row 0..767][8 x 16B]; rows 0-511 enc, 512-767 dec.
// 16B cols: logical 0-3 = w_hi(k 0..31 of chunk), 4-7 = w_lo; stored col = logical ^ (row&7).
__device__ uint4 g_wsplit[8][768][8];

__global__ void prep_kernel(const float* __restrict__ enc_w, const float* __restrict__ dec_w) {
    int idx = blockIdx.x * blockDim.x + threadIdx.x;
    if (idx >= 768 * 32) return;
    int row = idx >> 5, c8 = idx & 31;
    const float* src = (row < 512) ? (enc_w + row * 256 + c8 * 8)
                                   : (dec_w + (row - 512) * 256 + c8 * 8);
    union { __half h[8]; uint4 u; } hi, lo;
#pragma unroll
    for (int i = 0; i < 8; i++) {
        float v = src[i];
        hi.h[i] = __float2half(v);
        lo.h[i] = __float2half(v - __half2float(hi.h[i]));
    }
    int chunk = c8 >> 2, lc = c8 & 3;
    g_wsplit[chunk][row][lc ^ (row & 7)]       = hi.u;
    g_wsplit[chunk][row][(lc + 4) ^ (row & 7)] = lo.u;
}

static __device__ __forceinline__ uint32_t smem_u32(const void* p) {
    uint32_t a;
    asm("{ .reg .u64 t; cvta.to.shared.u64 t, %1; cvt.u32.u64 %0, t; }" : "=r"(a) : "l"(p));
    return a;
}
static __device__ __forceinline__ void ldm4(uint32_t* d, uint32_t a) {
    asm volatile("ldmatrix.sync.aligned.m8n8.x4.shared.b16 {%0,%1,%2,%3}, [%4];"
                 : "=r"(d[0]), "=r"(d[1]), "=r"(d[2]), "=r"(d[3]) : "r"(a));
}
static __device__ __forceinline__ void mma16816(float* c, const uint32_t* a, const uint32_t* b) {
    asm volatile("mma.sync.aligned.m16n8k16.row.col.f32.f16.f16.f32 "
                 "{%0,%1,%2,%3}, {%4,%5,%6,%7}, {%8,%9}, {%0,%1,%2,%3};"
                 : "+f"(c[0]), "+f"(c[1]), "+f"(c[2]), "+f"(c[3])
                 : "r"(a[0]), "r"(a[1]), "r"(a[2]), "r"(a[3]), "r"(b[0]), "r"(b[1]));
}

// stage one 32KB weight chunk (rows r*256..+255) into ABUF buffer `buf` via cp.async
static __device__ __forceinline__ void stage_chunk(uint32_t sb, int r, int chunk, int buf, int tid) {
    int row = tid >> 1, half = tid & 1;
    const uint4* gsrc = &g_wsplit[chunk][r * 256 + row][half * 4];
    uint32_t dstb = sb + ABUF + (uint32_t)buf * 32768u + (uint32_t)row * 128u + (uint32_t)half * 64u;
#pragma unroll
    for (int i = 0; i < 4; i++)
        asm volatile("cp.async.cg.shared.global [%0], [%1], 16;"
                     :: "r"(dstb + i * 16), "l"(gsrc + i) : "memory");
    asm volatile("cp.async.commit_group;" ::: "memory");
}

__global__ __launch_bounds__(THREADS, 1)
void NeuralSpectralBlock1d_4509715661385_kernel(
    const float* __restrict__ x, const float* __restrict__ weights,
    const float* __restrict__ latent, const float* __restrict__ enc_b,
    const float* __restrict__ dec_b, float* __restrict__ out)
{
    extern __shared__ char smem[];
    const uint32_t sb = smem_u32(smem);

    float* lt_s  = (float*)(smem + LT);    // [256][66]
    float* w_s   = (float*)(smem + WS);    // [256][24]
    float* lat_s = (float*)(smem + LAT);
    float* eb_s  = (float*)(smem + EB);
    float* db_s  = (float*)(smem + DB);
    float* stg   = (float*)(smem + ABUF);  // epilogue: [256][65]

    const int tid = threadIdx.x;
    const int wid = tid >> 5, lid = tid & 31;
    const int bx = blockIdx.x;
    const int batch = bx >> 6;
    const int hp0 = (bx & 63) * 16;
    const int h0 = hp0 * 4;
    const float* xg = x + (size_t)batch * 256 * 4096 + h0;
    float* og = out + (size_t)batch * 256 * 4096;

    // prefetch round-0 chunk-0 weights (overlaps with x load)
    stage_chunk(sb, 0, 0, 0, tid);

    // ---- load x tile -> XTHI (n-major [64][256] fp16, 16B col swizzled by n) ----
    for (int idx = tid; idx < 64 * 256; idx += THREADS) {
        int j = idx & 63, c = idx >> 6;
        float v = xg[(size_t)c * 4096 + j];
        uint32_t off = (uint32_t)j * 512u + ((uint32_t)((c >> 3) ^ (j & 7)) << 4) + (uint32_t)(c & 7) * 2u;
        *(__half*)(smem + XTHI + off) = __float2half(v);
    }
    for (int idx = tid; idx < 256 * 24; idx += THREADS) w_s[idx] = weights[idx];
    for (int idx = tid; idx < 1024; idx += THREADS) lat_s[idx] = latent[idx];
    for (int idx = tid; idx < 512; idx += THREADS) eb_s[idx] = enc_b[idx];
    for (int idx = tid; idx < 256; idx += THREADS) db_s[idx] = dec_b[idx];

    // epilogue lane roles
    const int g256 = tid >> 8;            // thread half-group
    const int t = tid & 255;
    const int ip = t >> 4;
    const int lane4 = t & 15;
    const int la = lane4 >> 2, lb = lane4 & 3;
    const unsigned FULL = 0xFFFFFFFFu;
    const float PI_OVER_NB = 0.26179938779914943653855361527329f;  // pi/12

    // GEMM warp roles: wm = M slice (32 rows), wn = N half (32 cols)
    const int wm = wid & 7, wn = wid >> 3;
    const int a_row8 = (lid & 7) + ((lid >> 3) & 1) * 8;
    const int a_half = lid >> 4;
    const int b_n8   = (lid & 7) + ((lid >> 4) & 1) * 8;
    const int b_k8   = (lid >> 3) & 1;

    // ================= 3 GEMM rounds: r=0,1 enc; r=2 dec =================
#pragma unroll 1
    for (int r = 0; r < 3; r++) {
        float acc[2][4][4];
#pragma unroll
        for (int mt = 0; mt < 2; mt++)
#pragma unroll
            for (int nt = 0; nt < 4; nt++)
#pragma unroll
                for (int q = 0; q < 4; q++) acc[mt][nt][q] = 0.f;

#pragma unroll 1
        for (int c = 0; c < 8; c++) {
            if (c < 7) {
                stage_chunk(sb, r, c + 1, (c + 1) & 1, tid);
                asm volatile("cp.async.wait_group 1;" ::: "memory");
            } else {
                asm volatile("cp.async.wait_group 0;" ::: "memory");
            }
            __syncthreads();

            const uint32_t ab = sb + ABUF + (uint32_t)(c & 1) * 32768u;
#pragma unroll
            for (int s = 0; s < 2; s++) {
                uint32_t ah[2][4], al[2][4];
#pragma unroll
                for (int mt = 0; mt < 2; mt++) {
                    int row = wm * 32 + mt * 16 + a_row8;
                    int lch = 2 * s + a_half;
                    ldm4(ah[mt], ab + (uint32_t)row * 128u + ((uint32_t)(lch ^ (row & 7)) << 4));
                    int lcl = 4 + 2 * s + a_half;
                    ldm4(al[mt], ab + (uint32_t)row * 128u + ((uint32_t)(lcl ^ (row & 7)) << 4));
                }
                uint32_t bh[2][4];
#pragma unroll
                for (int nb = 0; nb < 2; nb++) {
                    int n = (2 * wn + nb) * 16 + b_n8;
                    int col = c * 4 + 2 * s + b_k8;
                    uint32_t off = (uint32_t)n * 512u + ((uint32_t)(col ^ (n & 7)) << 4);
                    ldm4(bh[nb], sb + XTHI + off);
                }
#pragma unroll
                for (int mt = 0; mt < 2; mt++)
#pragma unroll
                    for (int nt = 0; nt < 4; nt++) {
                        const uint32_t* B0 = &bh[nt >> 1][(nt & 1) * 2];
                        mma16816(acc[mt][nt], ah[mt], B0);   // w_hi * x
                        mma16816(acc[mt][nt], al[mt], B0);   // w_lo * x
                    }
            }
            __syncthreads();
        }

        // ---------------- dump (all 16 warps) ----------------
        {
            const float* bias = (r < 2) ? (eb_s + r * 256) : db_s;
#pragma unroll
            for (int mt = 0; mt < 2; mt++) {
                int r0 = wm * 32 + mt * 16 + (lid >> 2);
                float b0 = bias[r0], b8 = bias[r0 + 8];
#pragma unroll
                for (int nt = 0; nt < 4; nt++) {
                    int cc0 = wn * 32 + nt * 8 + (lid & 3) * 2;
                    stg[r0 * 65 + cc0]           = acc[mt][nt][0] + b0;
                    stg[r0 * 65 + cc0 + 1]       = acc[mt][nt][1] + b0;
                    stg[(r0 + 8) * 65 + cc0]     = acc[mt][nt][2] + b8;
                    stg[(r0 + 8) * 65 + cc0 + 1] = acc[mt][nt][3] + b8;
                }
            }
        }
        __syncthreads();

        if (r < 2) {
            // ===== encoder epilogue: group g256 handles heads r*4+g*2 .. +1 =====
#pragma unroll 1
            for (int hl = 0; hl < 2; hl++) {
                int h = r * 4 + g256 * 2 + hl;
                int rowb = g256 * 128 + hl * 64;
                const float* qv = lat_s + h * 128 + la * 32;
                float sc = 0.f;
#pragma unroll
                for (int d = 0; d < 32; d++)
                    sc += qv[d] * stg[(rowb + 2 * d) * 65 + ip * 4 + lb];
                float mx = sc;
                mx = fmaxf(mx, __shfl_xor_sync(FULL, mx, 1, 4));
                mx = fmaxf(mx, __shfl_xor_sync(FULL, mx, 2, 4));
                float ex = __expf(sc - mx);
                float ssum = ex;
                ssum += __shfl_xor_sync(FULL, ssum, 1, 4);
                ssum += __shfl_xor_sync(FULL, ssum, 2, 4);
                float av = ex / ssum;
                float a4[4];
#pragma unroll
                for (int s2 = 0; s2 < 4; s2++) a4[s2] = __shfl_sync(FULL, av, la * 4 + s2, 16);

#pragma unroll 1
                for (int dd = 0; dd < 8; dd++) {
                    int d = lb + 4 * dd;
                    float ltv = lat_s[h * 128 + la * 32 + d];
#pragma unroll
                    for (int s2 = 0; s2 < 4; s2++)
                        ltv += a4[s2] * stg[(rowb + 2 * d + 1) * 65 + ip * 4 + s2];
                    int cch = h * 32 + d;
                    const float* wc = w_s + cch * 24;
                    float s1, c1;
                    __sincosf(ltv * PI_OVER_NB, &s1, &c1);
                    float sM = 0.f, cM = 1.f;
                    float add = wc[12];
#pragma unroll
                    for (int m = 1; m < 12; m++) {
                        float ns = sM * c1 + cM * s1;
                        float nc = cM * c1 - sM * s1;
                        sM = ns; cM = nc;
                        add += ns * wc[m] + nc * wc[12 + m];
                    }
                    lt_s[cch * 66 + ip * 4 + la] = ltv + add;
                }
            }
        } else {
            // ===== decoder epilogue: group g256 handles heads g*4 .. g*4+3 =====
#pragma unroll 1
            for (int hl = 0; hl < 4; hl++) {
                int h = g256 * 4 + hl;
                int rowb = g256 * 128 + hl * 32;
                float sc = 0.f;
#pragma unroll
                for (int d = 0; d < 32; d++)
                    sc += stg[(rowb + d) * 65 + ip * 4 + la] *
                          lt_s[(h * 32 + d) * 66 + ip * 4 + lb];
                float mx = sc;
                mx = fmaxf(mx, __shfl_xor_sync(FULL, mx, 1, 4));
                mx = fmaxf(mx, __shfl_xor_sync(FULL, mx, 2, 4));
                float ex = __expf(sc - mx);
                float ssum = ex;
                ssum += __shfl_xor_sync(FULL, ssum, 1, 4);
                ssum += __shfl_xor_sync(FULL, ssum, 2, 4);
                float av = ex / ssum;
                float a4[4];
#pragma unroll
                for (int t2 = 0; t2 < 4; t2++) a4[t2] = __shfl_sync(FULL, av, la * 4 + t2, 16);

                int j = ip * 4 + la;
#pragma unroll 1
                for (int dd = 0; dd < 8; dd++) {
                    int d = lb + 4 * dd;
                    int cch = h * 32 + d;
                    float o = 0.f;
#pragma unroll
                    for (int t2 = 0; t2 < 4; t2++)
                        o += a4[t2] * lt_s[cch * 66 + ip * 4 + t2];
                    uint32_t off = (uint32_t)j * 512u +
                                   ((uint32_t)((cch >> 3) ^ (j & 7)) << 4) + (uint32_t)(cch & 7) * 2u;
                    float xr = __half2float(*(__half*)(smem + XTHI + off));
                    og[(size_t)la * 262144 + (size_t)(hp0 + ip) * 256 + cch] = o + xr;
                }
            }
        }
        __syncthreads();   // stg region reused by next round's staging

        if (r < 2) stage_chunk(sb, r + 1, 0, 0, tid);   // prefetch next round chunk 0
    }
}

extern "C" void kernel_launch(void* const* d_in, const int* in_sizes, int n_in,
                              void* d_out, int out_size)
{
    const float* x       = (const float*)d_in[0];
    const float* weights = (const float*)d_in[1];
    const float* latent  = (const float*)d_in[2];
    const float* enc_w   = (const float*)d_in[3];
    const float* enc_b   = (const float*)d_in[4];
    const float* dec_w   = (const float*)d_in[5];
    const float* dec_b   = (const float*)d_in[6];
    float* out = (float*)d_out;

    prep_kernel<<<(768 * 32 + 255) / 256, 256>>>(enc_w, dec_w);

    cudaFuncSetAttribute(NeuralSpectralBlock1d_4509715661385_kernel,
                         cudaFuncAttributeMaxDynamicSharedMemorySize, (int)SMEM_REQ);
    NeuralSpectralBlock1d_4509715661385_kernel<<<2048, THREADS, SMEM_REQ>>>(
        x, weights, latent, enc_b, dec_b, out);
}